// round 2
// baseline (speedup 1.0000x reference)
#include <cuda_runtime.h>
#include <cuda_bf16.h>

// Output of reference = minimum(y, 0.25) then clip(0.25, 1.0) == 0.25 everywhere,
// independent of inputs (all finite). Pure constant fill -> HBM-write-bound.
//
// R2: persistent grid-stride fill with 4-way unrolled streaming (evict-first)
// 128-bit stores. Fixes R1's one-store-per-CTA launch churn (occ 24%) and L2
// dirty-line thrash (244 MB output vs 126 MB L2).

#define MIN_VALUE 0.25f

__global__ void __launch_bounds__(256) fill_const_persist(float4* __restrict__ out4,
                                                          long long n4) {
    const float4 v = make_float4(MIN_VALUE, MIN_VALUE, MIN_VALUE, MIN_VALUE);
    const long long stride = (long long)gridDim.x * blockDim.x;
    long long i = (long long)blockIdx.x * blockDim.x + threadIdx.x;

    // 4-way unrolled main loop: 4 independent STG.128 in flight per thread.
    for (; i + 3 * stride < n4; i += 4 * stride) {
        __stcs(&out4[i],              v);
        __stcs(&out4[i + stride],     v);
        __stcs(&out4[i + 2 * stride], v);
        __stcs(&out4[i + 3 * stride], v);
    }
    // Remainder
    for (; i < n4; i += stride) {
        __stcs(&out4[i], v);
    }
}

__global__ void fill_const_tail(float* __restrict__ out, long long start, long long n) {
    long long i = start + (long long)blockIdx.x * blockDim.x + threadIdx.x;
    if (i < n) {
        out[i] = MIN_VALUE;
    }
}

extern "C" void kernel_launch(void* const* d_in, const int* in_sizes, int n_in,
                              void* d_out, int out_size) {
    (void)d_in; (void)in_sizes; (void)n_in;

    long long n = (long long)out_size;
    long long n4 = n >> 2;              // number of float4 stores
    long long tail_start = n4 << 2;

    const int threads = 256;

    if (n4 > 0) {
        // 148 SMs x 8 CTAs: enough warps to keep DRAM queues full, no CTA churn.
        int blocks = 148 * 8;
        long long max_useful = (n4 + threads - 1) / threads;
        if ((long long)blocks > max_useful) blocks = (int)max_useful;
        fill_const_persist<<<blocks, threads>>>((float4*)d_out, n4);
    }
    if (tail_start < n) {
        long long tail = n - tail_start;
        long long blocks = (tail + threads - 1) / threads;
        fill_const_tail<<<(unsigned int)blocks, threads>>>((float*)d_out, tail_start, n);
    }
}

// round 3
// speedup vs baseline: 1.1116x; 1.1116x over previous
#include <cuda_runtime.h>
#include <cuda_bf16.h>

// Output of reference = minimum(y, 0.25) then clip(0.25, 1.0) == 0.25 everywhere,
// independent of inputs (all finite). Pure constant fill -> store-bound.
//
// R3: CTA-contiguous blocked fill. Each CTA owns 2048 consecutive float4s
// (32 KB); each thread issues 8 independent 128-bit stores (default caching —
// L2 write-absorb overlaps DRAM drain with the next graph replay). Keeps R1's
// sequential address ordering, fixes its MLP=1 / 59K-CTA launch churn.

#define MIN_VALUE 0.25f
#define UNROLL 8
#define THREADS 256

__global__ void __launch_bounds__(THREADS) fill_const_blocked(float4* __restrict__ out4,
                                                              long long n4) {
    const float4 v = make_float4(MIN_VALUE, MIN_VALUE, MIN_VALUE, MIN_VALUE);
    long long base = (long long)blockIdx.x * (THREADS * UNROLL) + threadIdx.x;

#pragma unroll
    for (int j = 0; j < UNROLL; j++) {
        long long i = base + (long long)j * THREADS;
        if (i < n4) {
            out4[i] = v;
        }
    }
}

__global__ void fill_const_tail(float* __restrict__ out, long long start, long long n) {
    long long i = start + (long long)blockIdx.x * blockDim.x + threadIdx.x;
    if (i < n) {
        out[i] = MIN_VALUE;
    }
}

extern "C" void kernel_launch(void* const* d_in, const int* in_sizes, int n_in,
                              void* d_out, int out_size) {
    (void)d_in; (void)in_sizes; (void)n_in;

    long long n = (long long)out_size;
    long long n4 = n >> 2;              // number of float4 stores
    long long tail_start = n4 << 2;

    if (n4 > 0) {
        const long long per_cta = (long long)THREADS * UNROLL;
        long long blocks = (n4 + per_cta - 1) / per_cta;
        fill_const_blocked<<<(unsigned int)blocks, THREADS>>>((float4*)d_out, n4);
    }
    if (tail_start < n) {
        long long tail = n - tail_start;
        long long blocks = (tail + THREADS - 1) / THREADS;
        fill_const_tail<<<(unsigned int)blocks, THREADS>>>((float*)d_out, tail_start, n);
    }
}